// round 13
// baseline (speedup 1.0000x reference)
#include <cuda_runtime.h>
#include <cuda_bf16.h>
#include <cuda_fp16.h>
#include <cstdint>

// ---------------------------------------------------------------- constants
#define N_TOK   2048
#define CBN     8
#define DIM     32
#define NROWS   16384
#define KCODES  16384
#define MTILES  (NROWS / 16)       // 1024 m16 tiles
#define NTILES  (KCODES / 8)       // 2048 n8 tiles
#define NSPLIT  32
#define TPS     (NTILES / NSPLIT)  // 64 n-tiles per split
#define GRP     4                  // tiles per candidate group (8 codes)
#define NGRP    (TPS / GRP)        // 16 groups per split
#define NCAND   256                // 32 splits x 4 threads x 2 (top-2 groups)

// Output layout: zhat [2048,256] | kl_loss [1] | indices [2048,8] (as float)
#define ZHAT_OFF 0
#define KL_OFF   524288
#define IDX_OFF  524289

// ---------------------------------------------------------------- scratch
__device__ float g_w1[NROWS * DIM];               // 0.5*(1 - 1/var)  (bit-exact)
__device__ float g_w2[NROWS * DIM];               // mu / var         (bit-exact)
__device__ uint4 g_Afp[MTILES * 4 * 32];          // [mt][kstep][lane] a0..a3 fp16x2
__device__ uint2 g_B2[(size_t)NTILES * 32 * 4];   // [(nt*32+lane)*4 + ks] {b0,b1}
__device__ int   g_ci[(size_t)NROWS * NCAND];     // candidate GROUP base columns
__device__ float g_cv[(size_t)NROWS * NCAND];     // group-max approx values
__device__ float g_klpart[2048];

// ---------------------------------------------------------------- helpers
__device__ __forceinline__ uint32_t hpack(float x, float y) {
    __half2 h = __floats2half2_rn(x, y);
    return *(uint32_t*)&h;
}

#define MMA4(d0, d1, d2, d3, a, b0, b1) \
    asm volatile("mma.sync.aligned.m16n8k16.row.col.f32.f16.f16.f32 " \
        "{%0,%1,%2,%3}, {%4,%5,%6,%7}, {%8,%9}, {%0,%1,%2,%3};" \
        : "+f"(d0), "+f"(d1), "+f"(d2), "+f"(d3) \
        : "r"((a).x), "r"((a).y), "r"((a).z), "r"((a).w), "r"(b0), "r"(b1))

__device__ __forceinline__ void upd2(float v, int idx,
                                     float& v1, int& i1, float& v2, int& i2) {
    if (v > v2) {
        if (v > v1) { v2 = v1; i2 = i1; v1 = v; i1 = idx; }
        else        { v2 = v;  i2 = idx; }
    }
}

// Approx weight recompute (fragments only; exact path uses g_w1/g_w2)
__device__ __forceinline__ float compw(const float* __restrict__ z, int row, int f) {
    int t  = row >> 3;
    int cb = row & 7;
    if (f < 32) {
        float lv = z[t * 512 + 256 + f * CBN + cb];
        lv = fminf(fmaxf(lv, -30.0f), 20.0f);
        return 0.5f * (1.0f - expf(-lv));
    } else {
        int d = f - 32;
        float mu = z[t * 512 + d * CBN + cb];
        float lv = z[t * 512 + 256 + d * CBN + cb];
        lv = fminf(fmaxf(lv, -30.0f), 20.0f);
        return mu * expf(-lv);
    }
}

// ---------------------------------------------------------------- fused prep
// blocks [0,2048): exact weights + KL partials
// blocks [2048,2560): A fragments (fp16) straight from z
// blocks [2560,3584): B fragments (fp16) from codebook
__global__ void __launch_bounds__(256) fused_prep(const float* __restrict__ z,
                                                  const float* __restrict__ codebook) {
    int b = blockIdx.x;
    if (b < 2048) {
        int idx = b * 256 + threadIdx.x;          // n*32 + d
        int n = idx >> 5;
        int d = idx & 31;
        int t  = n >> 3;
        int cb = n & 7;
        int j  = d * CBN + cb;

        float mu = z[t * 512 + j];
        float lv = z[t * 512 + 256 + j];
        lv = fminf(fmaxf(lv, -30.0f), 20.0f);
        float var = expf(lv);
        float sd  = expf(0.5f * lv);
        float inv = 1.0f / (sd * sd);

        g_w1[idx] = 0.5f * (1.0f - inv);
        g_w2[idx] = mu * inv;

        float klt = mu * mu + var - 1.0f - lv;
        __shared__ float sred[256];
        sred[threadIdx.x] = klt;
        __syncthreads();
        #pragma unroll
        for (int s = 128; s > 0; s >>= 1) {
            if (threadIdx.x < s) sred[threadIdx.x] += sred[threadIdx.x + s];
            __syncthreads();
        }
        if (threadIdx.x == 0) g_klpart[b] = sred[0];
    } else if (b < 2560) {
        int idx = (b - 2048) * 256 + threadIdx.x; // 131072 threads
        int lane = idx & 31;
        int ks   = (idx >> 5) & 3;
        int mt   = idx >> 7;

        int r0 = mt * 16 + (lane >> 2);
        int r1 = r0 + 8;
        int k0 = ks * 16 + (lane & 3) * 2;

        uint4 v;
        v.x = hpack(compw(z, r0, k0),     compw(z, r0, k0 + 1));
        v.y = hpack(compw(z, r1, k0),     compw(z, r1, k0 + 1));
        v.z = hpack(compw(z, r0, k0 + 8), compw(z, r0, k0 + 9));
        v.w = hpack(compw(z, r1, k0 + 8), compw(z, r1, k0 + 9));

        g_Afp[(mt * 4 + ks) * 32 + lane] = v;
    } else {
        int idx = (b - 2560) * 256 + threadIdx.x; // 262144 threads
        int lane = idx & 31;
        int ks   = (idx >> 5) & 3;
        int nt   = idx >> 7;

        int n  = nt * 8 + (lane >> 2);
        int k0 = ks * 16 + (lane & 3) * 2;
        const float* cr = codebook + (size_t)n * 32;

        float y0, y1, y2, y3;
        {
            int f = k0;
            y0 = (f < 32) ? cr[f] * cr[f] : cr[f - 32];
            y1 = (f + 1 < 32) ? cr[f + 1] * cr[f + 1] : cr[f + 1 - 32];
            f = k0 + 8;
            y2 = (f < 32) ? cr[f] * cr[f] : cr[f - 32];
            y3 = (f + 1 < 32) ? cr[f + 1] * cr[f + 1] : cr[f + 1 - 32];
        }

        uint2 v;
        v.x = hpack(y0, y1);
        v.y = hpack(y2, y3);
        g_B2[((size_t)nt * 32 + lane) * 4 + ks] = v;
    }
}

// ---------------------------------------------------------------- score
// 128 thr = 4 warps; warp owns FOUR m16 tiles (B loads amortized 4x).
// grid (MTILES/16, NSPLIT=32). Flat tile loop, unroll GRP=4; candidates at
// GROUP granularity with the group merge statically inside the unrolled body.
__global__ void __launch_bounds__(128, 3) score_mma() {
    int warp = threadIdx.x >> 5;
    int lane = threadIdx.x & 31;
    int mt0  = (blockIdx.x * 4 + warp) * 4;       // first of four m-tiles

    uint4 A[4][4];
    #pragma unroll
    for (int j = 0; j < 4; ++j)
        #pragma unroll
        for (int ks = 0; ks < 4; ++ks)
            A[j][ks] = g_Afp[((mt0 + j) * 4 + ks) * 32 + lane];

    int t0 = blockIdx.y * TPS;
    const uint4* bp = (const uint4*)g_B2 + ((size_t)t0 * 32 + lane) * 2;
    int colg = t0 * 8 + (lane & 3) * 2;           // group base column

    float v1[8], v2[8], gm[8];
    int   i1[8], i2[8];
    #pragma unroll
    for (int r = 0; r < 8; ++r) {
        v1[r] = -INFINITY; v2[r] = -INFINITY; gm[r] = -INFINITY;
        i1[r] = 0; i2[r] = 0;
    }

    #pragma unroll 4
    for (int t = 0; t < TPS; ++t) {
        uint4 B0 = bp[0];
        uint4 B1 = bp[1];
        bp += 64;

        #pragma unroll
        for (int j = 0; j < 4; ++j) {
            float d0 = 0.f, d1 = 0.f, d2 = 0.f, d3 = 0.f;
            MMA4(d0, d1, d2, d3, A[j][0], B0.x, B0.y);
            MMA4(d0, d1, d2, d3, A[j][1], B0.z, B0.w);
            MMA4(d0, d1, d2, d3, A[j][2], B1.x, B1.y);
            MMA4(d0, d1, d2, d3, A[j][3], B1.z, B1.w);
            gm[2 * j]     = fmaxf(gm[2 * j],     fmaxf(d0, d1));
            gm[2 * j + 1] = fmaxf(gm[2 * j + 1], fmaxf(d2, d3));
        }

        if ((t & 3) == 3) {                       // static under unroll 4
            #pragma unroll
            for (int r = 0; r < 8; ++r) {
                upd2(gm[r], colg, v1[r], i1[r], v2[r], i2[r]);
                gm[r] = -INFINITY;
            }
            colg += 8 * GRP;
        }
    }

    int cbase = blockIdx.y * 8 + (lane & 3) * 2;
    #pragma unroll
    for (int j = 0; j < 4; ++j) {
        #pragma unroll
        for (int h = 0; h < 2; ++h) {
            int row = (mt0 + j) * 16 + (lane >> 2) + 8 * h;
            size_t rr = (size_t)row * NCAND + cbase;
            g_ci[rr]     = i1[2 * j + h];
            g_ci[rr + 1] = i2[2 * j + h];
            g_cv[rr]     = v1[2 * j + h];
            g_cv[rr + 1] = v2[2 * j + h];
        }
    }
}

// ---------------------------------------------------------------- finalize
// Warp per row. Prefilter by approx group-max vs rigorous fp16 margin;
// exact-rescore all 8 codes of surviving groups. Compact loops (unroll 1).
__global__ void __launch_bounds__(256) finalize_kernel(const float* __restrict__ codebook,
                                                       float* __restrict__ out) {
    int warp = threadIdx.x >> 5;
    int lane = threadIdx.x & 31;
    int n = blockIdx.x * 8 + warp;     // 0..16383

    float w1r[DIM], w2r[DIM];
    {
        const float4* a = (const float4*)(g_w1 + (size_t)n * DIM);
        const float4* b = (const float4*)(g_w2 + (size_t)n * DIM);
        #pragma unroll
        for (int q = 0; q < 8; ++q) {
            ((float4*)w1r)[q] = a[q];
            ((float4*)w2r)[q] = b[q];
        }
    }

    float cvv[8]; int cii[8];
    float vmax = -INFINITY;
    #pragma unroll
    for (int e = 0; e < 8; ++e) {
        cvv[e] = g_cv[(size_t)n * NCAND + e * 32 + lane];
        cii[e] = g_ci[(size_t)n * NCAND + e * 32 + lane];
        vmax = fmaxf(vmax, cvv[e]);
    }
    #pragma unroll
    for (int off = 16; off > 0; off >>= 1)
        vmax = fmaxf(vmax, __shfl_xor_sync(0xFFFFFFFF, vmax, off));

    // rigorous fp16 margin: per-term rel err 2^-11, x2 operands, x2 slack;
    // |c| < 5, c^2 < 25 over N(0,1) codebook. 2e-3 absorbs expf(-lv) vs
    // 1/sd^2 difference in the approx fragments.
    float S = 0.0f;
    #pragma unroll
    for (int d = 0; d < DIM; ++d)
        S = fmaf(fabsf(w1r[d]), 25.0f, fmaf(fabsf(w2r[d]), 5.0f, S));
    float thr = vmax - (S * (1.0f / 512.0f) + 2e-3f);

    float bv = -INFINITY;
    int   bi = 0x7FFFFFFF;
    #pragma unroll 1
    for (int e = 0; e < 8; ++e) {
        if (cvv[e] < thr) continue;
        int base = cii[e];
        #pragma unroll 1
        for (int k = 0; k < 8; ++k) {          // 8 codes of the group
            int ci = base + (k >> 1) * 8 + (k & 1);
            const float4* cr = (const float4*)(codebook + (size_t)ci * DIM);
            float a0 = 0.f, a1 = 0.f;
            #pragma unroll
            for (int q = 0; q < 8; ++q) {
                float4 cv = cr[q];
                int d = q * 4;
                a0 = fmaf(w1r[d],     cv.x * cv.x, a0);  a0 = fmaf(w2r[d],     cv.x, a0);
                a1 = fmaf(w1r[d + 1], cv.y * cv.y, a1);  a1 = fmaf(w2r[d + 1], cv.y, a1);
                a0 = fmaf(w1r[d + 2], cv.z * cv.z, a0);  a0 = fmaf(w2r[d + 2], cv.z, a0);
                a1 = fmaf(w1r[d + 3], cv.w * cv.w, a1);  a1 = fmaf(w2r[d + 3], cv.w, a1);
            }
            float s = a0 + a1;
            if (s > bv || (s == bv && ci < bi)) { bv = s; bi = ci; }
        }
    }
    #pragma unroll
    for (int off = 16; off > 0; off >>= 1) {
        float ov = __shfl_xor_sync(0xFFFFFFFF, bv, off);
        int   oi = __shfl_xor_sync(0xFFFFFFFF, bi, off);
        if (ov > bv || (ov == bv && oi < bi)) { bv = ov; bi = oi; }
    }

    int t  = n >> 3;
    int cb = n & 7;
    float cval = codebook[(size_t)bi * DIM + lane];
    out[ZHAT_OFF + t * 256 + lane * CBN + cb] = cval;
    if (lane == 0) out[IDX_OFF + n] = (float)bi;

    if (blockIdx.x == 0) {
        __shared__ float s[256];
        float acc = 0.0f;
        #pragma unroll
        for (int i = 0; i < 8; ++i) acc += g_klpart[threadIdx.x * 8 + i];
        s[threadIdx.x] = acc;
        __syncthreads();
        #pragma unroll
        for (int st = 128; st > 0; st >>= 1) {
            if (threadIdx.x < st) s[threadIdx.x] += s[threadIdx.x + st];
            __syncthreads();
        }
        if (threadIdx.x == 0)
            out[KL_OFF] = (float)((double)s[0] * (1.4426 * 0.5 / 16384.0));
    }
}

// ----------------------------------------------------------------
extern "C" void kernel_launch(void* const* d_in, const int* in_sizes, int n_in,
                              void* d_out, int out_size) {
    const float* z        = (const float*)d_in[0];   // [4,512,512]
    // d_in[1] = noise: dead in forward value (STE)
    const float* codebook = (const float*)d_in[2];   // [16384,32]
    float* out = (float*)d_out;

    fused_prep<<<3584, 256>>>(z, codebook);
    score_mma<<<dim3(MTILES / 16, NSPLIT), 128>>>();
    finalize_kernel<<<NROWS / 8, 256>>>(codebook, out);
}

// round 14
// speedup vs baseline: 1.4027x; 1.4027x over previous
#include <cuda_runtime.h>
#include <cuda_bf16.h>
#include <cuda_fp16.h>
#include <cstdint>

// ---------------------------------------------------------------- constants
#define N_TOK   2048
#define CBN     8
#define DIM     32
#define NROWS   16384
#define KCODES  16384
#define MTILES  (NROWS / 16)       // 1024 m16 tiles
#define NTILES  (KCODES / 8)       // 2048 n8 tiles
#define NSPLIT  16
#define TPS     (NTILES / NSPLIT)  // 128 n-tiles per split
#define NQ      2                  // subsets per split
#define TPQ     (TPS / NQ)         // 64 tiles per subset
#define NCAND   256                // 16 splits x 2 subsets x 4 threads x 2 pairs

// Output layout: zhat [2048,256] | kl_loss [1] | indices [2048,8] (as float)
#define ZHAT_OFF 0
#define KL_OFF   524288
#define IDX_OFF  524289

// ---------------------------------------------------------------- scratch
__device__ float g_w1[NROWS * DIM];               // 0.5*(1 - 1/var)  (bit-exact)
__device__ float g_w2[NROWS * DIM];               // mu / var         (bit-exact)
__device__ uint4 g_Afp[MTILES * 4 * 32];          // [mt][kstep][lane] a0..a3 fp16x2
// B frags, warp-coalesced: [nt][half][lane] uint4; half0={ks0,ks1}, half1={ks2,ks3}
__device__ uint4 g_B4[(size_t)NTILES * 64];
__device__ int   g_ci[(size_t)NROWS * NCAND];     // candidate PAIR base columns
__device__ float g_cv[(size_t)NROWS * NCAND];     // pair-max approx values
__device__ float g_klpart[2048];

// ---------------------------------------------------------------- helpers
__device__ __forceinline__ uint32_t hpack(float x, float y) {
    __half2 h = __floats2half2_rn(x, y);
    return *(uint32_t*)&h;
}

#define MMA4(d0, d1, d2, d3, a, b0, b1) \
    asm volatile("mma.sync.aligned.m16n8k16.row.col.f32.f16.f16.f32 " \
        "{%0,%1,%2,%3}, {%4,%5,%6,%7}, {%8,%9}, {%0,%1,%2,%3};" \
        : "+f"(d0), "+f"(d1), "+f"(d2), "+f"(d3) \
        : "r"((a).x), "r"((a).y), "r"((a).z), "r"((a).w), "r"(b0), "r"(b1))

__device__ __forceinline__ void upd2(float v, int idx,
                                     float& v1, int& i1, float& v2, int& i2) {
    if (v > v2) {
        if (v > v1) { v2 = v1; i2 = i1; v1 = v; i1 = idx; }
        else        { v2 = v;  i2 = idx; }
    }
}

// Approx weight recompute (fragments only; exact path uses g_w1/g_w2)
__device__ __forceinline__ float compw(const float* __restrict__ z, int row, int f) {
    int t  = row >> 3;
    int cb = row & 7;
    if (f < 32) {
        float lv = z[t * 512 + 256 + f * CBN + cb];
        lv = fminf(fmaxf(lv, -30.0f), 20.0f);
        return 0.5f * (1.0f - expf(-lv));
    } else {
        int d = f - 32;
        float mu = z[t * 512 + d * CBN + cb];
        float lv = z[t * 512 + 256 + d * CBN + cb];
        lv = fminf(fmaxf(lv, -30.0f), 20.0f);
        return mu * expf(-lv);
    }
}

// ---------------------------------------------------------------- fused prep
// blocks [0,2048): exact weights + KL partials
// blocks [2048,2560): A fragments (fp16) straight from z
// blocks [2560,3584): B fragments (fp16) from codebook, warp-coalesced layout
__global__ void __launch_bounds__(256) fused_prep(const float* __restrict__ z,
                                                  const float* __restrict__ codebook) {
    int b = blockIdx.x;
    if (b < 2048) {
        int idx = b * 256 + threadIdx.x;          // n*32 + d
        int n = idx >> 5;
        int d = idx & 31;
        int t  = n >> 3;
        int cb = n & 7;
        int j  = d * CBN + cb;

        float mu = z[t * 512 + j];
        float lv = z[t * 512 + 256 + j];
        lv = fminf(fmaxf(lv, -30.0f), 20.0f);
        float var = expf(lv);
        float sd  = expf(0.5f * lv);
        float inv = 1.0f / (sd * sd);

        g_w1[idx] = 0.5f * (1.0f - inv);
        g_w2[idx] = mu * inv;

        float klt = mu * mu + var - 1.0f - lv;
        __shared__ float sred[256];
        sred[threadIdx.x] = klt;
        __syncthreads();
        #pragma unroll
        for (int s = 128; s > 0; s >>= 1) {
            if (threadIdx.x < s) sred[threadIdx.x] += sred[threadIdx.x + s];
            __syncthreads();
        }
        if (threadIdx.x == 0) g_klpart[b] = sred[0];
    } else if (b < 2560) {
        int idx = (b - 2048) * 256 + threadIdx.x; // 131072 threads
        int lane = idx & 31;
        int ks   = (idx >> 5) & 3;
        int mt   = idx >> 7;

        int r0 = mt * 16 + (lane >> 2);
        int r1 = r0 + 8;
        int k0 = ks * 16 + (lane & 3) * 2;

        uint4 v;
        v.x = hpack(compw(z, r0, k0),     compw(z, r0, k0 + 1));
        v.y = hpack(compw(z, r1, k0),     compw(z, r1, k0 + 1));
        v.z = hpack(compw(z, r0, k0 + 8), compw(z, r0, k0 + 9));
        v.w = hpack(compw(z, r1, k0 + 8), compw(z, r1, k0 + 9));

        g_Afp[(mt * 4 + ks) * 32 + lane] = v;
    } else {
        int idx = (b - 2560) * 256 + threadIdx.x; // 262144 threads
        int lane = idx & 31;
        int ks   = (idx >> 5) & 3;
        int nt   = idx >> 7;

        int n  = nt * 8 + (lane >> 2);
        int k0 = ks * 16 + (lane & 3) * 2;
        const float* cr = codebook + (size_t)n * 32;

        float y0, y1, y2, y3;
        {
            int f = k0;
            y0 = (f < 32) ? cr[f] * cr[f] : cr[f - 32];
            y1 = (f + 1 < 32) ? cr[f + 1] * cr[f + 1] : cr[f + 1 - 32];
            f = k0 + 8;
            y2 = (f < 32) ? cr[f] * cr[f] : cr[f - 32];
            y3 = (f + 1 < 32) ? cr[f + 1] * cr[f + 1] : cr[f + 1 - 32];
        }

        // warp-coalesced layout: uint2 index = nt*128 + (ks>>1)*64 + lane*2 + (ks&1)
        uint2 v;
        v.x = hpack(y0, y1);
        v.y = hpack(y2, y3);
        ((uint2*)g_B4)[(size_t)nt * 128 + (ks >> 1) * 64 + lane * 2 + (ks & 1)] = v;
    }
}

// ---------------------------------------------------------------- score
// (R12 structure; only B layout changed to lane-contiguous -> 4 wf/LDG.128)
// 128 thr = 4 warps; warp owns TWO m16 tiles. grid (MTILES/8, NSPLIT=16).
__global__ void __launch_bounds__(128, 5) score_mma() {
    int warp = threadIdx.x >> 5;
    int lane = threadIdx.x & 31;
    int mt0  = (blockIdx.x * 4 + warp) * 2;

    uint4 a0[4], a1[4];
    #pragma unroll
    for (int ks = 0; ks < 4; ++ks) {
        a0[ks] = g_Afp[(mt0 * 4 + ks) * 32 + lane];
        a1[ks] = g_Afp[((mt0 + 1) * 4 + ks) * 32 + lane];
    }

    int t0 = blockIdx.y * TPS;
    const uint4* bp = g_B4 + (size_t)t0 * 64 + lane;
    int col = t0 * 8 + (lane & 3) * 2;

    int rbase = mt0 * 16 + (lane >> 2);

    for (int q = 0; q < NQ; ++q) {
        float v1A = -INFINITY, v2A = -INFINITY; int i1A = 0, i2A = 0;
        float v1B = -INFINITY, v2B = -INFINITY; int i1B = 0, i2B = 0;
        float v1C = -INFINITY, v2C = -INFINITY; int i1C = 0, i2C = 0;
        float v1D = -INFINITY, v2D = -INFINITY; int i1D = 0, i2D = 0;

        #pragma unroll 4
        for (int t = 0; t < TPQ; ++t) {
            uint4 B0 = bp[0];
            uint4 B1 = bp[32];
            bp += 64;

            float d0 = 0.f, d1 = 0.f, d2 = 0.f, d3 = 0.f;
            float e0 = 0.f, e1 = 0.f, e2 = 0.f, e3 = 0.f;
            MMA4(d0, d1, d2, d3, a0[0], B0.x, B0.y);
            MMA4(e0, e1, e2, e3, a1[0], B0.x, B0.y);
            MMA4(d0, d1, d2, d3, a0[1], B0.z, B0.w);
            MMA4(e0, e1, e2, e3, a1[1], B0.z, B0.w);
            MMA4(d0, d1, d2, d3, a0[2], B1.x, B1.y);
            MMA4(e0, e1, e2, e3, a1[2], B1.x, B1.y);
            MMA4(d0, d1, d2, d3, a0[3], B1.z, B1.w);
            MMA4(e0, e1, e2, e3, a1[3], B1.z, B1.w);

            upd2(fmaxf(d0, d1), col, v1A, i1A, v2A, i2A);
            upd2(fmaxf(d2, d3), col, v1B, i1B, v2B, i2B);
            upd2(fmaxf(e0, e1), col, v1C, i1C, v2C, i2C);
            upd2(fmaxf(e2, e3), col, v1D, i1D, v2D, i2D);
            col += 8;
        }

        int cbase = blockIdx.y * (NQ * 8) + q * 8 + (lane & 3) * 2;
        size_t rA = (size_t)rbase * NCAND + cbase;
        size_t rB = (size_t)(rbase + 8)  * NCAND + cbase;
        size_t rC = (size_t)(rbase + 16) * NCAND + cbase;
        size_t rD = (size_t)(rbase + 24) * NCAND + cbase;
        g_ci[rA] = i1A; g_ci[rA + 1] = i2A; g_cv[rA] = v1A; g_cv[rA + 1] = v2A;
        g_ci[rB] = i1B; g_ci[rB + 1] = i2B; g_cv[rB] = v1B; g_cv[rB + 1] = v2B;
        g_ci[rC] = i1C; g_ci[rC + 1] = i2C; g_cv[rC] = v1C; g_cv[rC + 1] = v2C;
        g_ci[rD] = i1D; g_ci[rD + 1] = i2D; g_cv[rD] = v1D; g_cv[rD + 1] = v2D;
    }
}

// ---------------------------------------------------------------- finalize
// (R12/R10 version) Warp per row; prefilter + exact pair rescore.
__global__ void __launch_bounds__(256) finalize_kernel(const float* __restrict__ codebook,
                                                       float* __restrict__ out) {
    int warp = threadIdx.x >> 5;
    int lane = threadIdx.x & 31;
    int n = blockIdx.x * 8 + warp;     // 0..16383

    float w1r[DIM], w2r[DIM];
    {
        const float4* a = (const float4*)(g_w1 + (size_t)n * DIM);
        const float4* b = (const float4*)(g_w2 + (size_t)n * DIM);
        #pragma unroll
        for (int q = 0; q < 8; ++q) {
            ((float4*)w1r)[q] = a[q];
            ((float4*)w2r)[q] = b[q];
        }
    }

    float cvv[8]; int cii[8];
    float vmax = -INFINITY;
    #pragma unroll
    for (int e = 0; e < 8; ++e) {
        cvv[e] = g_cv[(size_t)n * NCAND + e * 32 + lane];
        cii[e] = g_ci[(size_t)n * NCAND + e * 32 + lane];
        vmax = fmaxf(vmax, cvv[e]);
    }
    #pragma unroll
    for (int off = 16; off > 0; off >>= 1)
        vmax = fmaxf(vmax, __shfl_xor_sync(0xFFFFFFFF, vmax, off));

    // rigorous fp16 margin: per-term rel err 2^-11, x2 operands, x2 slack;
    // |c| < 5, c^2 < 25 over N(0,1) codebook. 2e-3 absorbs expf(-lv) vs
    // 1/sd^2 difference in the approx fragments.
    float S = 0.0f;
    #pragma unroll
    for (int d = 0; d < DIM; ++d)
        S = fmaf(fabsf(w1r[d]), 25.0f, fmaf(fabsf(w2r[d]), 5.0f, S));
    float thr = vmax - (S * (1.0f / 512.0f) + 2e-3f);

    float bv = -INFINITY;
    int   bi = 0x7FFFFFFF;
    #pragma unroll 1
    for (int e = 0; e < 8; ++e) {
        if (cvv[e] < thr) continue;
        #pragma unroll 1
        for (int h = 0; h < 2; ++h) {          // both columns of the pair
            int ci = cii[e] + h;
            const float4* cr = (const float4*)(codebook + (size_t)ci * DIM);
            float a0 = 0.f, a1 = 0.f;
            #pragma unroll
            for (int q = 0; q < 8; ++q) {
                float4 cv = cr[q];
                int d = q * 4;
                a0 = fmaf(w1r[d],     cv.x * cv.x, a0);  a0 = fmaf(w2r[d],     cv.x, a0);
                a1 = fmaf(w1r[d + 1], cv.y * cv.y, a1);  a1 = fmaf(w2r[d + 1], cv.y, a1);
                a0 = fmaf(w1r[d + 2], cv.z * cv.z, a0);  a0 = fmaf(w2r[d + 2], cv.z, a0);
                a1 = fmaf(w1r[d + 3], cv.w * cv.w, a1);  a1 = fmaf(w2r[d + 3], cv.w, a1);
            }
            float s = a0 + a1;
            if (s > bv || (s == bv && ci < bi)) { bv = s; bi = ci; }
        }
    }
    #pragma unroll
    for (int off = 16; off > 0; off >>= 1) {
        float ov = __shfl_xor_sync(0xFFFFFFFF, bv, off);
        int   oi = __shfl_xor_sync(0xFFFFFFFF, bi, off);
        if (ov > bv || (ov == bv && oi < bi)) { bv = ov; bi = oi; }
    }

    int t  = n >> 3;
    int cb = n & 7;
    float cval = codebook[(size_t)bi * DIM + lane];
    out[ZHAT_OFF + t * 256 + lane * CBN + cb] = cval;
    if (lane == 0) out[IDX_OFF + n] = (float)bi;

    if (blockIdx.x == 0) {
        __shared__ float s[256];
        float acc = 0.0f;
        #pragma unroll
        for (int i = 0; i < 8; ++i) acc += g_klpart[threadIdx.x * 8 + i];
        s[threadIdx.x] = acc;
        __syncthreads();
        #pragma unroll
        for (int st = 128; st > 0; st >>= 1) {
            if (threadIdx.x < st) s[threadIdx.x] += s[threadIdx.x + st];
            __syncthreads();
        }
        if (threadIdx.x == 0)
            out[KL_OFF] = (float)((double)s[0] * (1.4426 * 0.5 / 16384.0));
    }
}

// ----------------------------------------------------------------
extern "C" void kernel_launch(void* const* d_in, const int* in_sizes, int n_in,
                              void* d_out, int out_size) {
    const float* z        = (const float*)d_in[0];   // [4,512,512]
    // d_in[1] = noise: dead in forward value (STE)
    const float* codebook = (const float*)d_in[2];   // [16384,32]
    float* out = (float*)d_out;

    fused_prep<<<3584, 256>>>(z, codebook);
    score_mma<<<dim3(MTILES / 8, NSPLIT), 128>>>();
    finalize_kernel<<<NROWS / 8, 256>>>(codebook, out);
}